// round 2
// baseline (speedup 1.0000x reference)
#include <cuda_runtime.h>
#include <math.h>

// ---------------- problem constants ----------------
#define BATCH   4
#define SEQ     2048
#define DIM     1024
#define NHEADS  8
#define HDIM    128
#define WINDOW  16
#define EPSV    1e-6f
#define MROWS   (BATCH * SEQ)          // 8192

// ---------------- device scratch (static; no runtime allocs) ----------------
__device__ float g_xq[MROWS * DIM];
__device__ float g_xk[MROWS * DIM];
__device__ float g_xv[MROWS * DIM];
__device__ float g_y [MROWS * DIM];

// ---------------- SGEMM: C[M,N] = A[M,K] @ B[K,N], fp32 ----------------
#define BM 128
#define BN 128
#define BK 8
#define TM 8
#define TN 8

__global__ __launch_bounds__(256, 2)
void sgemm_kernel(const float* __restrict__ A, const float* __restrict__ B,
                  float* __restrict__ C, int M, int N, int K)
{
    __shared__ float As[BK][BM];
    __shared__ float Bs[BK][BN];

    const int tid = threadIdx.x;
    const int bm = blockIdx.y * BM;
    const int bn = blockIdx.x * BN;

    // load indexing
    const int a_row = tid >> 1;            // 0..127
    const int a_col = (tid & 1) * 4;       // 0 or 4
    const int b_row = tid >> 5;            // 0..7
    const int b_col = (tid & 31) * 4;      // 0..124

    const float* Aptr = A + (size_t)(bm + a_row) * K;
    const float* Bptr = B + bn;

    // compute indexing: 16x16 grid of threads, each 8x8 outputs
    const int ty = (tid >> 4) * TM;        // 0..120
    const int tx = (tid & 15) * TN;        // 0..120

    float acc[TM][TN];
#pragma unroll
    for (int i = 0; i < TM; i++)
#pragma unroll
        for (int j = 0; j < TN; j++) acc[i][j] = 0.0f;

    for (int k0 = 0; k0 < K; k0 += BK) {
        float4 av = *(const float4*)(Aptr + k0 + a_col);
        float4 bv = *(const float4*)(Bptr + (size_t)(k0 + b_row) * N + b_col);
        As[a_col + 0][a_row] = av.x;
        As[a_col + 1][a_row] = av.y;
        As[a_col + 2][a_row] = av.z;
        As[a_col + 3][a_row] = av.w;
        *(float4*)&Bs[b_row][b_col] = bv;
        __syncthreads();

#pragma unroll
        for (int kk = 0; kk < BK; kk++) {
            float ar[TM], br[TN];
            float4 a0 = *(const float4*)&As[kk][ty];
            float4 a1 = *(const float4*)&As[kk][ty + 4];
            float4 b0 = *(const float4*)&Bs[kk][tx];
            float4 b1 = *(const float4*)&Bs[kk][tx + 4];
            ar[0]=a0.x; ar[1]=a0.y; ar[2]=a0.z; ar[3]=a0.w;
            ar[4]=a1.x; ar[5]=a1.y; ar[6]=a1.z; ar[7]=a1.w;
            br[0]=b0.x; br[1]=b0.y; br[2]=b0.z; br[3]=b0.w;
            br[4]=b1.x; br[5]=b1.y; br[6]=b1.z; br[7]=b1.w;
#pragma unroll
            for (int i = 0; i < TM; i++)
#pragma unroll
                for (int j = 0; j < TN; j++)
                    acc[i][j] = fmaf(ar[i], br[j], acc[i][j]);
        }
        __syncthreads();
    }

    float* Cptr = C + (size_t)(bm + ty) * N + bn + tx;
#pragma unroll
    for (int i = 0; i < TM; i++) {
        float4 v0 = {acc[i][0], acc[i][1], acc[i][2], acc[i][3]};
        float4 v1 = {acc[i][4], acc[i][5], acc[i][6], acc[i][7]};
        *(float4*)(Cptr + (size_t)i * N)     = v0;
        *(float4*)(Cptr + (size_t)i * N + 4) = v1;
    }
}

// ---------------- RMSNorm (in place, row = 1024 floats) ----------------
__global__ __launch_bounds__(256)
void rmsnorm_kernel(float* __restrict__ x, const float* __restrict__ w)
{
    const int row = blockIdx.x;
    const int tid = threadIdx.x;
    float* xr = x + (size_t)row * DIM;

    // each thread owns one float4 (256*4 = 1024)
    float4 v = *(const float4*)(xr + tid * 4);
    float ss = v.x*v.x + v.y*v.y + v.z*v.z + v.w*v.w;

    __shared__ float red[8];
#pragma unroll
    for (int o = 16; o; o >>= 1) ss += __shfl_xor_sync(0xFFFFFFFFu, ss, o);
    if ((tid & 31) == 0) red[tid >> 5] = ss;
    __syncthreads();
    if (tid < 32) {
        float s = (tid < 8) ? red[tid] : 0.0f;
#pragma unroll
        for (int o = 4; o; o >>= 1) s += __shfl_xor_sync(0xFFFFFFFFu, s, o);
        if (tid == 0) red[0] = s;
    }
    __syncthreads();

    const float rs = rsqrtf(red[0] * (1.0f / DIM) + EPSV);
    float4 wv = *(const float4*)(w + tid * 4);
    v.x *= rs * wv.x; v.y *= rs * wv.y; v.z *= rs * wv.z; v.w *= rs * wv.w;
    *(float4*)(xr + tid * 4) = v;
}

// ---------------- banded attention: one warp per (b, t, h) ----------------
__global__ __launch_bounds__(256)
void attn_kernel(const float* __restrict__ xq, const float* __restrict__ xk,
                 const float* __restrict__ xv, float* __restrict__ y)
{
    const int gw   = (blockIdx.x * blockDim.x + threadIdx.x) >> 5;
    const int lane = threadIdx.x & 31;
    // gw decodes as (b, t, h); total B*T*H warps
    const int h = gw & (NHEADS - 1);
    const int t = (gw >> 3) & (SEQ - 1);
    const int b = gw >> 14;                       // SEQ*NHEADS = 16384

    const size_t rowq = ((size_t)(b * SEQ + t)) * DIM + h * HDIM;
    const float4 q = *(const float4*)(xq + rowq + lane * 4);

    const float scale = 0.08838834764831845f;     // 1/sqrt(128)
    const float slope = exp2f(-(float)h);         // ALiBi slopes for H=8

    float scores[WINDOW + 1];
    float mx = -1e30f;

#pragma unroll
    for (int jj = 0; jj <= WINDOW; jj++) {
        const int j = t - WINDOW + jj;
        float s = -1e30f;
        if (j >= 0) {
            const size_t rowk = ((size_t)(b * SEQ + j)) * DIM + h * HDIM;
            const float4 k = *(const float4*)(xk + rowk + lane * 4);
            float d = q.x*k.x + q.y*k.y + q.z*k.z + q.w*k.w;
#pragma unroll
            for (int o = 16; o; o >>= 1) d += __shfl_xor_sync(0xFFFFFFFFu, d, o);
            s = d * scale + slope * (float)(j - t);
        }
        scores[jj] = s;
        mx = fmaxf(mx, s);
    }

    float l = 0.0f;
#pragma unroll
    for (int jj = 0; jj <= WINDOW; jj++) {
        float e = __expf(scores[jj] - mx);
        scores[jj] = e;
        l += e;
    }
    const float inv = 1.0f / l;

    float4 acc = {0.f, 0.f, 0.f, 0.f};
#pragma unroll
    for (int jj = 0; jj <= WINDOW; jj++) {
        const int j = t - WINDOW + jj;
        if (j >= 0) {
            const size_t rowv = ((size_t)(b * SEQ + j)) * DIM + h * HDIM;
            const float4 v = *(const float4*)(xv + rowv + lane * 4);
            const float p = scores[jj] * inv;
            acc.x = fmaf(p, v.x, acc.x);
            acc.y = fmaf(p, v.y, acc.y);
            acc.z = fmaf(p, v.z, acc.z);
            acc.w = fmaf(p, v.w, acc.w);
        }
    }
    *(float4*)(y + rowq + lane * 4) = acc;
}

// ---------------- launch ----------------
extern "C" void kernel_launch(void* const* d_in, const int* in_sizes, int n_in,
                              void* d_out, int out_size)
{
    const float* x       = (const float*)d_in[0];
    const float* wq      = (const float*)d_in[1];
    const float* wk      = (const float*)d_in[2];
    const float* wv      = (const float*)d_in[3];
    const float* wo      = (const float*)d_in[4];
    const float* qnw     = (const float*)d_in[5];
    const float* knw     = (const float*)d_in[6];
    float* out           = (float*)d_out;

    float *xq, *xk, *xv, *y;
    cudaGetSymbolAddress((void**)&xq, g_xq);
    cudaGetSymbolAddress((void**)&xk, g_xk);
    cudaGetSymbolAddress((void**)&xv, g_xv);
    cudaGetSymbolAddress((void**)&y,  g_y);

    dim3 ggrid(DIM / BN, MROWS / BM);   // (8, 64)
    dim3 gblk(256);

    // QKV projections
    sgemm_kernel<<<ggrid, gblk>>>(x, wq, xq, MROWS, DIM, DIM);
    sgemm_kernel<<<ggrid, gblk>>>(x, wk, xk, MROWS, DIM, DIM);
    sgemm_kernel<<<ggrid, gblk>>>(x, wv, xv, MROWS, DIM, DIM);

    // RMSNorm on q and k (full 1024-dim rows)
    rmsnorm_kernel<<<MROWS, 256>>>(xq, qnw);
    rmsnorm_kernel<<<MROWS, 256>>>(xk, knw);

    // banded attention: B*T*H warps, 8 warps per block
    const int total_warps = BATCH * SEQ * NHEADS;     // 65536
    attn_kernel<<<total_warps / 8, 256>>>(xq, xk, xv, y);

    // output projection
    sgemm_kernel<<<ggrid, gblk>>>(y, wo, out, MROWS, DIM, DIM);
}

// round 4
// speedup vs baseline: 2.3418x; 2.3418x over previous
#include <cuda_runtime.h>
#include <cuda_bf16.h>
#include <math.h>
#include <stdint.h>

// ---------------- problem constants ----------------
#define BATCH 4
#define SEQ   2048
#define DIM   1024
#define NH    8
#define HD    128
#define WIN   16
#define EPSV  1e-6f
#define MR    (BATCH*SEQ)   // 8192
#define NQKV  3072

// ---------------- device scratch ----------------
__device__ __align__(16) __nv_bfloat16 g_xhi[MR*DIM];
__device__ __align__(16) __nv_bfloat16 g_xlo[MR*DIM];
__device__ __align__(16) __nv_bfloat16 g_wqkvT_hi[NQKV*DIM];
__device__ __align__(16) __nv_bfloat16 g_wqkvT_lo[NQKV*DIM];
__device__ __align__(16) __nv_bfloat16 g_woT_hi[DIM*DIM];
__device__ __align__(16) __nv_bfloat16 g_woT_lo[DIM*DIM];
__device__ __align__(16) float         g_qkv[MR*NQKV];
__device__ __align__(16) __nv_bfloat16 g_yhi[MR*DIM];
__device__ __align__(16) __nv_bfloat16 g_ylo[MR*DIM];

// ---------------- PTX helpers (baseline features only; NO tcgen05/TMA) ----------------
__device__ __forceinline__ uint32_t smem_u32(const void* p) {
    uint32_t a;
    asm("{ .reg .u64 t; cvta.to.shared.u64 t, %1; cvt.u32.u64 %0, t; }" : "=r"(a) : "l"(p));
    return a;
}
__device__ __forceinline__ void cp16(uint32_t d, const void* s) {
    asm volatile("cp.async.cg.shared.global [%0], [%1], 16;" :: "r"(d), "l"(s));
}
__device__ __forceinline__ void cp_commit() { asm volatile("cp.async.commit_group;" ::: "memory"); }
__device__ __forceinline__ void cp_wait2()  { asm volatile("cp.async.wait_group 2;" ::: "memory"); }
__device__ __forceinline__ void cp_wait1()  { asm volatile("cp.async.wait_group 1;" ::: "memory"); }
__device__ __forceinline__ void cp_wait0()  { asm volatile("cp.async.wait_group 0;" ::: "memory"); }

__device__ __forceinline__ void ldm_x4(uint32_t* r, uint32_t addr) {
    asm volatile("ldmatrix.sync.aligned.m8n8.x4.shared.b16 {%0,%1,%2,%3}, [%4];"
                 : "=r"(r[0]), "=r"(r[1]), "=r"(r[2]), "=r"(r[3]) : "r"(addr));
}
__device__ __forceinline__ void ldm_x2(uint32_t* r, uint32_t addr) {
    asm volatile("ldmatrix.sync.aligned.m8n8.x2.shared.b16 {%0,%1}, [%2];"
                 : "=r"(r[0]), "=r"(r[1]) : "r"(addr));
}
__device__ __forceinline__ void mma16816(float* c, const uint32_t* a, const uint32_t* b) {
    asm volatile(
        "mma.sync.aligned.m16n8k16.row.col.f32.bf16.bf16.f32 "
        "{%0,%1,%2,%3}, {%4,%5,%6,%7}, {%8,%9}, {%0,%1,%2,%3};"
        : "+f"(c[0]), "+f"(c[1]), "+f"(c[2]), "+f"(c[3])
        : "r"(a[0]), "r"(a[1]), "r"(a[2]), "r"(a[3]), "r"(b[0]), "r"(b[1]));
}

// ---------------- hi/lo split of x ----------------
__global__ __launch_bounds__(256)
void split_kernel(const float* __restrict__ x, __nv_bfloat16* __restrict__ hi,
                  __nv_bfloat16* __restrict__ lo, int n4)
{
    int i = blockIdx.x * 256 + threadIdx.x;
    if (i >= n4) return;
    float4 v = ((const float4*)x)[i];
    __nv_bfloat16 h0 = __float2bfloat16(v.x), h1 = __float2bfloat16(v.y);
    __nv_bfloat16 h2 = __float2bfloat16(v.z), h3 = __float2bfloat16(v.w);
    __nv_bfloat162 H0; H0.x = h0; H0.y = h1;
    __nv_bfloat162 H1; H1.x = h2; H1.y = h3;
    ((__nv_bfloat162*)hi)[2*i]   = H0;
    ((__nv_bfloat162*)hi)[2*i+1] = H1;
    __nv_bfloat162 L0, L1;
    L0.x = __float2bfloat16(v.x - __bfloat162float(h0));
    L0.y = __float2bfloat16(v.y - __bfloat162float(h1));
    L1.x = __float2bfloat16(v.z - __bfloat162float(h2));
    L1.y = __float2bfloat16(v.w - __bfloat162float(h3));
    ((__nv_bfloat162*)lo)[2*i]   = L0;
    ((__nv_bfloat162*)lo)[2*i+1] = L1;
}

// ---------------- transpose + split weights: W[K=1024][N'=1024] -> WT[N'][K] hi/lo ----------------
__global__ __launch_bounds__(256)
void transpose_split(const float* __restrict__ W, __nv_bfloat16* __restrict__ hi,
                     __nv_bfloat16* __restrict__ lo)
{
    __shared__ float t[32][33];
    const int c0 = blockIdx.x * 32, r0 = blockIdx.y * 32;
    const int tx = threadIdx.x, ty = threadIdx.y;
#pragma unroll
    for (int j = 0; j < 4; j++)
        t[ty + 8*j][tx] = W[(size_t)(r0 + ty + 8*j) * DIM + c0 + tx];
    __syncthreads();
#pragma unroll
    for (int j = 0; j < 4; j++) {
        float v = t[tx][ty + 8*j];
        __nv_bfloat16 h = __float2bfloat16(v);
        size_t o = (size_t)(c0 + ty + 8*j) * DIM + (r0 + tx);
        hi[o] = h;
        lo[o] = __float2bfloat16(v - __bfloat162float(h));
    }
}

// ---------------- warp-MMA GEMM: C[m0:+128][n0:+128] += A[M,1024] @ B[N,1024]^T ----------------
// bf16 hi/lo 3-pass (hi*hi + hi*lo + lo*hi), fp32 accum.
// CTA 128x128, BK=32, 4-stage cp.async pipeline, 8 warps of 64x32.
#define BKE   32                 // bf16 elements per K chunk
#define TILEB 8192               // 128 rows x 64 bytes
#define STAGEB (4*TILEB)         // Ahi, Alo, Bhi, Blo
#define NSTAGE 4
#define GSMEM  (NSTAGE*STAGEB)   // 131072

// swizzled chunk address inside a 128x64B tile
__device__ __forceinline__ uint32_t swz_addr(uint32_t tile, int row, int chunk) {
    return tile + row * 64 + (((uint32_t)(chunk ^ ((row >> 1) & 3))) << 4);
}

__device__ __forceinline__ void ld_tile32(uint32_t sdst, const __nv_bfloat16* g,
                                          int grow0, int k0, int lrow, int lc0)
{
    const __nv_bfloat16* src = g + (size_t)(grow0 + lrow) * DIM + k0 + lc0 * 8;
    cp16(swz_addr(sdst, lrow, lc0),     src);
    cp16(swz_addr(sdst, lrow, lc0 + 1), src + 8);
}

__global__ __launch_bounds__(256, 1)
void gemm_bf16split(const __nv_bfloat16* __restrict__ ahi, const __nv_bfloat16* __restrict__ alo,
                    const __nv_bfloat16* __restrict__ bhi, const __nv_bfloat16* __restrict__ blo,
                    float* __restrict__ C, int ldc)
{
    extern __shared__ char smem[];
    const uint32_t sbase = smem_u32(smem);
    const int tid  = threadIdx.x;
    const int lane = tid & 31;
    const int wid  = tid >> 5;
    const int wm   = wid >> 2;          // 0..1  -> 64-row strip
    const int wn   = wid & 3;           // 0..3  -> 32-col strip
    const int m0 = blockIdx.y * 128;
    const int n0 = blockIdx.x * 128;

    // loader indices: each thread fills 2 chunks per tile, 4 tiles per stage
    const int lrow = tid >> 1;          // 0..127
    const int lc0  = (tid & 1) * 2;     // 0 or 2

    // fragment address components
    int arow[4], brow[4];
#pragma unroll
    for (int mt = 0; mt < 4; mt++) arow[mt] = wm * 64 + mt * 16 + (lane & 15);
#pragma unroll
    for (int nt = 0; nt < 4; nt++) brow[nt] = wn * 32 + nt * 8 + (lane & 7);
    const int ac = lane >> 4;           // A chunk selector (0/1)
    const int bc = (lane >> 3) & 1;     // B chunk selector (0/1)

    float acc[4][4][4];
#pragma unroll
    for (int mt = 0; mt < 4; mt++)
#pragma unroll
        for (int nt = 0; nt < 4; nt++)
#pragma unroll
            for (int q = 0; q < 4; q++) acc[mt][nt][q] = 0.0f;

    // prologue: chunks 0..2 into stages 0..2
#pragma unroll
    for (int s = 0; s < 3; s++) {
        const uint32_t st = sbase + s * STAGEB;
        const int k0 = s * BKE;
        ld_tile32(st,             ahi, m0, k0, lrow, lc0);
        ld_tile32(st + TILEB,     alo, m0, k0, lrow, lc0);
        ld_tile32(st + 2*TILEB,   bhi, n0, k0, lrow, lc0);
        ld_tile32(st + 3*TILEB,   blo, n0, k0, lrow, lc0);
        cp_commit();
    }

    const int NIT = DIM / BKE;          // 32
    for (int i = 0; i < NIT; i++) {
        if (i < NIT - 2)      cp_wait2();
        else if (i == NIT-2)  cp_wait1();
        else                  cp_wait0();
        __syncthreads();

        if (i + 3 < NIT) {
            const uint32_t st = sbase + ((i + 3) & 3) * STAGEB;
            const int k0 = (i + 3) * BKE;
            ld_tile32(st,           ahi, m0, k0, lrow, lc0);
            ld_tile32(st + TILEB,   alo, m0, k0, lrow, lc0);
            ld_tile32(st + 2*TILEB, bhi, n0, k0, lrow, lc0);
            ld_tile32(st + 3*TILEB, blo, n0, k0, lrow, lc0);
            cp_commit();
        }

        const uint32_t st   = sbase + (i & 3) * STAGEB;
        const uint32_t sAhi = st;
        const uint32_t sAlo = st + TILEB;
        const uint32_t sBhi = st + 2*TILEB;
        const uint32_t sBlo = st + 3*TILEB;

#pragma unroll
        for (int kh = 0; kh < 2; kh++) {
            uint32_t fAhi[4][4], fAlo[4][4], fBhi[4][2], fBlo[4][2];
#pragma unroll
            for (int mt = 0; mt < 4; mt++) {
                ldm_x4(fAhi[mt], swz_addr(sAhi, arow[mt], kh * 2 + ac));
                ldm_x4(fAlo[mt], swz_addr(sAlo, arow[mt], kh * 2 + ac));
            }
#pragma unroll
            for (int nt = 0; nt < 4; nt++) {
                ldm_x2(fBhi[nt], swz_addr(sBhi, brow[nt], kh * 2 + bc));
                ldm_x2(fBlo[nt], swz_addr(sBlo, brow[nt], kh * 2 + bc));
            }
#pragma unroll
            for (int mt = 0; mt < 4; mt++)
#pragma unroll
                for (int nt = 0; nt < 4; nt++) {
                    mma16816(acc[mt][nt], fAhi[mt], fBhi[nt]);
                    mma16816(acc[mt][nt], fAhi[mt], fBlo[nt]);
                    mma16816(acc[mt][nt], fAlo[mt], fBhi[nt]);
                }
        }
    }

    // epilogue: direct float2 stores
    const int erow = lane >> 2;
    const int ecol = (lane & 3) * 2;
#pragma unroll
    for (int mt = 0; mt < 4; mt++) {
#pragma unroll
        for (int nt = 0; nt < 4; nt++) {
            const int r0 = m0 + wm * 64 + mt * 16 + erow;
            const int c0 = n0 + wn * 32 + nt * 8 + ecol;
            float2 v0 = {acc[mt][nt][0], acc[mt][nt][1]};
            float2 v1 = {acc[mt][nt][2], acc[mt][nt][3]};
            *(float2*)(C + (size_t)r0 * ldc + c0)       = v0;
            *(float2*)(C + (size_t)(r0 + 8) * ldc + c0) = v1;
        }
    }
}

// ---------------- RMSNorm over 1024 cols inside fused qkv rows ----------------
__global__ __launch_bounds__(256)
void rmsnorm_kernel(float* __restrict__ base, const float* __restrict__ w, int coloff)
{
    const int row = blockIdx.x;
    const int tid = threadIdx.x;
    float* xr = base + (size_t)row * NQKV + coloff;

    float4 v = *(const float4*)(xr + tid * 4);
    float ss = v.x*v.x + v.y*v.y + v.z*v.z + v.w*v.w;

    __shared__ float red[8];
#pragma unroll
    for (int o = 16; o; o >>= 1) ss += __shfl_xor_sync(0xFFFFFFFFu, ss, o);
    if ((tid & 31) == 0) red[tid >> 5] = ss;
    __syncthreads();
    if (tid < 32) {
        float s = (tid < 8) ? red[tid] : 0.0f;
#pragma unroll
        for (int o = 4; o; o >>= 1) s += __shfl_xor_sync(0xFFFFFFFFu, s, o);
        if (tid == 0) red[0] = s;
    }
    __syncthreads();

    const float rs = rsqrtf(red[0] * (1.0f / DIM) + EPSV);
    float4 wv = *(const float4*)(w + tid * 4);
    v.x *= rs * wv.x; v.y *= rs * wv.y; v.z *= rs * wv.z; v.w *= rs * wv.w;
    *(float4*)(xr + tid * 4) = v;
}

// ---------------- banded attention, smem-staged K/V window; outputs bf16 hi/lo ----------------
#define ASMEM (2 * 80 * 132 * 4)

__global__ __launch_bounds__(256)
void attn_kernel(const float* __restrict__ qkv, __nv_bfloat16* __restrict__ yhi,
                 __nv_bfloat16* __restrict__ ylo)
{
    extern __shared__ float sm[];
    float* ks = sm;
    float* vs = sm + 80 * 132;
    const int tid  = threadIdx.x;
    const int lane = tid & 31;
    const int wid  = tid >> 5;
    const int qb = blockIdx.x * 64;
    const int h  = blockIdx.y;
    const int b  = blockIdx.z;

    const float* kbase = qkv + (size_t)(b * SEQ) * NQKV + DIM     + h * HD;
    const float* vbase = qkv + (size_t)(b * SEQ) * NQKV + 2 * DIM + h * HD;

    for (int idx = tid; idx < 80 * 32; idx += 256) {
        const int r = idx >> 5, c = idx & 31;
        const int gr = qb - WIN + r;
        if (gr >= 0) {
            ((float4*)(ks + r * 132))[c] = ((const float4*)(kbase + (size_t)gr * NQKV))[c];
            ((float4*)(vs + r * 132))[c] = ((const float4*)(vbase + (size_t)gr * NQKV))[c];
        }
    }
    __syncthreads();

    const float scale = 0.08838834764831845f;   // 1/sqrt(128)
    const float slope = exp2f(-(float)h);       // ALiBi slope, H=8

#pragma unroll 1
    for (int it = 0; it < 8; it++) {
        const int t = qb + it * 8 + wid;
        const float4 q = *(const float4*)(qkv + (size_t)(b * SEQ + t) * NQKV + h * HD + lane * 4);

        float sc[WIN + 1];
        float mx = -1e30f;
#pragma unroll
        for (int jj = 0; jj <= WIN; jj++) {
            const int j = t - WIN + jj;
            float s = -1e30f;
            if (j >= 0) {
                const int sr = j - qb + WIN;
                const float4 k4 = *(const float4*)(ks + sr * 132 + lane * 4);
                float d = q.x*k4.x + q.y*k4.y + q.z*k4.z + q.w*k4.w;
#pragma unroll
                for (int o = 16; o; o >>= 1) d += __shfl_xor_sync(0xFFFFFFFFu, d, o);
                s = d * scale + slope * (float)(j - t);
            }
            sc[jj] = s;
            mx = fmaxf(mx, s);
        }
        float l = 0.0f;
#pragma unroll
        for (int jj = 0; jj <= WIN; jj++) {
            float e = __expf(sc[jj] - mx);
            sc[jj] = e;
            l += e;
        }
        const float inv = 1.0f / l;

        float4 acc = {0.f, 0.f, 0.f, 0.f};
#pragma unroll
        for (int jj = 0; jj <= WIN; jj++) {
            const int j = t - WIN + jj;
            if (j >= 0) {
                const int sr = j - qb + WIN;
                const float4 v4 = *(const float4*)(vs + sr * 132 + lane * 4);
                const float p = sc[jj] * inv;
                acc.x = fmaf(p, v4.x, acc.x);
                acc.y = fmaf(p, v4.y, acc.y);
                acc.z = fmaf(p, v4.z, acc.z);
                acc.w = fmaf(p, v4.w, acc.w);
            }
        }

        const size_t off = (size_t)(b * SEQ + t) * DIM + h * HD + lane * 4;
        __nv_bfloat16 h0 = __float2bfloat16(acc.x), h1 = __float2bfloat16(acc.y);
        __nv_bfloat16 h2 = __float2bfloat16(acc.z), h3 = __float2bfloat16(acc.w);
        __nv_bfloat162 H0; H0.x = h0; H0.y = h1;
        __nv_bfloat162 H1; H1.x = h2; H1.y = h3;
        ((__nv_bfloat162*)(yhi + off))[0] = H0;
        ((__nv_bfloat162*)(yhi + off))[1] = H1;
        __nv_bfloat162 L0, L1;
        L0.x = __float2bfloat16(acc.x - __bfloat162float(h0));
        L0.y = __float2bfloat16(acc.y - __bfloat162float(h1));
        L1.x = __float2bfloat16(acc.z - __bfloat162float(h2));
        L1.y = __float2bfloat16(acc.w - __bfloat162float(h3));
        ((__nv_bfloat162*)(ylo + off))[0] = L0;
        ((__nv_bfloat162*)(ylo + off))[1] = L1;
    }
}

// ---------------- launch ----------------
extern "C" void kernel_launch(void* const* d_in, const int* in_sizes, int n_in,
                              void* d_out, int out_size)
{
    const float* x   = (const float*)d_in[0];
    const float* wq  = (const float*)d_in[1];
    const float* wk  = (const float*)d_in[2];
    const float* wv  = (const float*)d_in[3];
    const float* wo  = (const float*)d_in[4];
    const float* qnw = (const float*)d_in[5];
    const float* knw = (const float*)d_in[6];
    float* out       = (float*)d_out;

    __nv_bfloat16 *xhi, *xlo, *wqkvhi, *wqkvlo, *wohi, *wolo, *yhi, *ylo;
    float *qkv;
    cudaGetSymbolAddress((void**)&xhi,    g_xhi);
    cudaGetSymbolAddress((void**)&xlo,    g_xlo);
    cudaGetSymbolAddress((void**)&wqkvhi, g_wqkvT_hi);
    cudaGetSymbolAddress((void**)&wqkvlo, g_wqkvT_lo);
    cudaGetSymbolAddress((void**)&wohi,   g_woT_hi);
    cudaGetSymbolAddress((void**)&wolo,   g_woT_lo);
    cudaGetSymbolAddress((void**)&qkv,    g_qkv);
    cudaGetSymbolAddress((void**)&yhi,    g_yhi);
    cudaGetSymbolAddress((void**)&ylo,    g_ylo);

    cudaFuncSetAttribute(gemm_bf16split, cudaFuncAttributeMaxDynamicSharedMemorySize, GSMEM);
    cudaFuncSetAttribute(attn_kernel,    cudaFuncAttributeMaxDynamicSharedMemorySize, ASMEM);

    // 1) split x into bf16 hi/lo
    split_kernel<<<(MR*DIM/4 + 255)/256, 256>>>(x, xhi, xlo, MR*DIM/4);

    // 2) transpose+split weights into [N][K] bf16 hi/lo
    dim3 tgrid(DIM/32, DIM/32), tblk(32, 8);
    transpose_split<<<tgrid, tblk>>>(wq, wqkvhi,            wqkvlo);
    transpose_split<<<tgrid, tblk>>>(wk, wqkvhi + 1024*DIM, wqkvlo + 1024*DIM);
    transpose_split<<<tgrid, tblk>>>(wv, wqkvhi + 2048*DIM, wqkvlo + 2048*DIM);
    transpose_split<<<tgrid, tblk>>>(wo, wohi,              wolo);

    // 3) fused QKV projection: [8192x1024] @ [1024x3072]
    dim3 qkvgrid(NQKV/128, MR/128);
    gemm_bf16split<<<qkvgrid, 256, GSMEM>>>(xhi, xlo, wqkvhi, wqkvlo, qkv, NQKV);

    // 4) RMSNorm on q and k slices
    rmsnorm_kernel<<<MR, 256>>>(qkv, qnw, 0);
    rmsnorm_kernel<<<MR, 256>>>(qkv, knw, DIM);

    // 5) banded attention -> y (bf16 hi/lo)
    dim3 agrid(SEQ/64, NH, BATCH);
    attn_kernel<<<agrid, 256, ASMEM>>>(qkv, yhi, ylo);

    // 6) output projection: [8192x1024] @ [1024x1024]
    dim3 ogrid(DIM/128, MR/128);
    gemm_bf16split<<<ogrid, 256, GSMEM>>>(yhi, ylo, wohi, wolo, out, DIM);
}